// round 16
// baseline (speedup 1.0000x reference)
#include <cuda_runtime.h>
#include <cuda_fp16.h>
#include <cstdint>
#include <cstddef>

#define BDIM 64
#define TDIM 512
#define DDIM 512
#define HDIM 1024
#define ODIM 512
#define G3   3072
#define MROWS 32768            // B*T
#define RCTA 128               // recurrence CTAs (single wave, 128 <= 148)
#define RJ   8                 // hidden units per recurrence CTA

// Scratch (device globals are the sanctioned no-alloc workaround)
__device__ float g_xall[(size_t)MROWS * G3];        // x projection, 402 MB
__device__ unsigned g_hfrag16[2][BDIM * HDIM / 2];  // h ping-pong (fp16, A-frag-major)
__device__ int g_sync[576];    // [i*32] i<16: group counters; [512]: root; [544]: flag

__device__ __forceinline__ unsigned f2tf32(float x) {
    unsigned r;
    asm("cvt.rna.tf32.f32 %0, %1;" : "=r"(r) : "f"(x));
    return r;
}

__device__ __forceinline__ unsigned packh2(float a, float b) {
    __half2 h = __floats2half2_rn(a, b);
    return *(unsigned*)&h;
}

__device__ __forceinline__ int ld_acq(const int* p) {
    int v;
    asm volatile("ld.global.acquire.gpu.s32 %0, [%1];" : "=r"(v) : "l"(p) : "memory");
    return v;
}

__device__ __forceinline__ void mma_tf32_k8(float* d,
    unsigned a0, unsigned a1, unsigned a2, unsigned a3,
    unsigned b0, unsigned b1)
{
    asm volatile(
        "mma.sync.aligned.m16n8k8.row.col.f32.tf32.tf32.f32 "
        "{%0,%1,%2,%3}, {%4,%5,%6,%7}, {%8,%9}, {%0,%1,%2,%3};\n"
        : "+f"(d[0]), "+f"(d[1]), "+f"(d[2]), "+f"(d[3])
        : "r"(a0), "r"(a1), "r"(a2), "r"(a3), "r"(b0), "r"(b1));
}

__device__ __forceinline__ void mma_f16_k16(float* d,
    unsigned a0, unsigned a1, unsigned a2, unsigned a3,
    unsigned b0, unsigned b1)
{
    asm volatile(
        "mma.sync.aligned.m16n8k16.row.col.f32.f16.f16.f32 "
        "{%0,%1,%2,%3}, {%4,%5,%6,%7}, {%8,%9}, {%0,%1,%2,%3};\n"
        : "+f"(d[0]), "+f"(d[1]), "+f"(d[2]), "+f"(d[3])
        : "r"(a0), "r"(a1), "r"(a2), "r"(a3), "r"(b0), "r"(b1));
}

__device__ __forceinline__ float sigmoidf_(float x) {
    return 1.0f / (1.0f + __expf(-x));
}
__device__ __forceinline__ float tanhf_(float x) {
    x = fminf(fmaxf(x, -15.0f), 15.0f);
    float e = __expf(-2.0f * x);
    return (1.0f - e) / (1.0f + e);
}

// One dummy launch keeps the recurrence kernel at ncu's -s 5 -c 1 slot.
__global__ void dummy_kernel() {}

// ---------------------------------------------------------------------------
// Generic NT GEMM: C[M,N] = A[M,K](rm) * B[N,K](rm)^T + bias[N]  (unchanged)
// ---------------------------------------------------------------------------
__global__ __launch_bounds__(256) void gemm_nt_kernel(
    const float* __restrict__ A, const float* __restrict__ B,
    const float* __restrict__ bias, float* __restrict__ C,
    int N, int K)
{
    __shared__ unsigned As[32][132];
    __shared__ unsigned Bs[32][132];
    const int tid  = threadIdx.x;
    const int lane = tid & 31;
    const int warp = tid >> 5;
    const int wm = warp & 3;
    const int wn = warp >> 2;
    const int g = lane >> 2;
    const int c = lane & 3;
    const int bm = blockIdx.y, bn = blockIdx.x;
    const float* Ab = A + (size_t)bm * 128 * K;
    const float* Bb = B + (size_t)bn * 128 * K;

    float acc[2][8][4];
#pragma unroll
    for (int i = 0; i < 2; i++)
#pragma unroll
        for (int j = 0; j < 8; j++)
#pragma unroll
            for (int e = 0; e < 4; e++) acc[i][j][e] = 0.0f;

    for (int k0 = 0; k0 < K; k0 += 32) {
        __syncthreads();
#pragma unroll
        for (int p = 0; p < 4; p++) {
            int flat = p * 256 + tid;
            int row = flat >> 3;
            int ks = (flat & 7) * 4;
            float4 va = *(const float4*)(Ab + (size_t)row * K + k0 + ks);
            As[ks + 0][row] = f2tf32(va.x);
            As[ks + 1][row] = f2tf32(va.y);
            As[ks + 2][row] = f2tf32(va.z);
            As[ks + 3][row] = f2tf32(va.w);
            float4 vb = *(const float4*)(Bb + (size_t)row * K + k0 + ks);
            Bs[ks + 0][row] = f2tf32(vb.x);
            Bs[ks + 1][row] = f2tf32(vb.y);
            Bs[ks + 2][row] = f2tf32(vb.z);
            Bs[ks + 3][row] = f2tf32(vb.w);
        }
        __syncthreads();
#pragma unroll
        for (int ks = 0; ks < 32; ks += 8) {
            unsigned a[2][4], b[8][2];
#pragma unroll
            for (int mt = 0; mt < 2; mt++) {
                int mb = wm * 32 + mt * 16;
                a[mt][0] = As[ks + c][mb + g];
                a[mt][1] = As[ks + c][mb + g + 8];
                a[mt][2] = As[ks + c + 4][mb + g];
                a[mt][3] = As[ks + c + 4][mb + g + 8];
            }
#pragma unroll
            for (int nt = 0; nt < 8; nt++) {
                int col = wn * 64 + nt * 8 + g;
                b[nt][0] = Bs[ks + c][col];
                b[nt][1] = Bs[ks + c + 4][col];
            }
#pragma unroll
            for (int mt = 0; mt < 2; mt++)
#pragma unroll
                for (int nt = 0; nt < 8; nt++)
                    mma_tf32_k8(acc[mt][nt], a[mt][0], a[mt][1], a[mt][2], a[mt][3],
                                b[nt][0], b[nt][1]);
        }
    }

#pragma unroll
    for (int mt = 0; mt < 2; mt++) {
        int row = bm * 128 + wm * 32 + mt * 16 + g;
#pragma unroll
        for (int nt = 0; nt < 8; nt++) {
            int col = bn * 128 + wn * 64 + nt * 8 + 2 * c;
            float b0 = bias[col], b1 = bias[col + 1];
            C[(size_t)row * N + col]           = acc[mt][nt][0] + b0;
            C[(size_t)row * N + col + 1]       = acc[mt][nt][1] + b1;
            C[(size_t)(row + 8) * N + col]     = acc[mt][nt][2] + b0;
            C[(size_t)(row + 8) * N + col + 1] = acc[mt][nt][3] + b1;
        }
    }
}

// ---------------------------------------------------------------------------
// Persistent GRU recurrence, fp16 / fp32-acc (R13 winner + two-level arrival
// tree). 128 CTAs (single wave), 256 threads (8 warps): mt = warp&3 (16 batch
// rows), kh = warp>>2 (K half, 32 k16-iters). Per iter: one a-frag LDG.128
// (.cg, 8-deep register ring) + 3 MMAs m16n8k16 (one n8 tile per gate).
// Wh SMEM-resident fp16 B-frags (48KB). Single 2-way K reduction. h_prev in
// epilogue registers; each CTA publishes HALF a kb-slot (one STG.64 per
// epilogue thread). Barrier: 16 groups x 8 arrivals on separate 128B lines
// (parallel LTS atomic chains) -> root counter -> release flag; hiddens STG
// + next-x prefetch hidden behind the wait.
// ---------------------------------------------------------------------------
extern __shared__ unsigned rec_smem[];   // Whs16[12288 u32] + red[1664 floats]

__global__ __launch_bounds__(256, 1) void gru_rec_kernel(
    const float* __restrict__ Wh, const float* __restrict__ bh,
    float* __restrict__ hiddens)
{
    unsigned* Whs = rec_smem;                       // [kb64][gate3][lane32][2]
    float* red = (float*)(rec_smem + 12288);        // [mt4*lane32][13]
    const int tid  = threadIdx.x;
    const int lane = tid & 31;
    const int warp = tid >> 5;
    const int mt = warp & 3;        // batch quarter (16 rows)
    const int kh = warp >> 2;       // K half (0..1)
    const int g = lane >> 2, c = lane & 3;
    const int bid = blockIdx.x;
    const int j0 = bid * RJ;

    // Load Wh slice -> SMEM in fp16 B-fragment order, once.
    for (int flat = tid; flat < 64 * 3 * 32; flat += 256) {
        int kb = flat / 96, rem = flat % 96;
        int gi = rem >> 5;            // gate
        int ln = rem & 31;
        int gg = ln >> 2, cc = ln & 3;
        const float* wp = Wh + (size_t)(gi * HDIM + j0 + gg) * HDIM + kb * 16 + 2 * cc;
        Whs[flat * 2 + 0] = packh2(wp[0], wp[1]);
        Whs[flat * 2 + 1] = packh2(wp[8], wp[9]);
    }

    const int jj = j0 + 2 * c;
    const int b0r = mt * 16 + g, b1r = b0r + 8;
    float bhv[3][2];                  // [gate][part]
#pragma unroll
    for (int gi = 0; gi < 3; gi++) {
        bhv[gi][0] = bh[gi * HDIM + jj];
        bhv[gi][1] = bh[gi * HDIM + jj + 1];
    }

    // Epilogue-warp persistent state: x_t prefetch and h_prev registers.
    float2 xv[3][2];
    float hpr[4];
#pragma unroll
    for (int e = 0; e < 4; e++) hpr[e] = 0.0f;
    if (kh == 0) {
#pragma unroll
        for (int gi = 0; gi < 3; gi++) {
            xv[gi][0] = *(const float2*)&g_xall[((size_t)b0r * TDIM) * G3 + gi * HDIM + jj];
            xv[gi][1] = *(const float2*)&g_xall[((size_t)b1r * TDIM) * G3 + gi * HDIM + jj];
        }
    }

    __syncthreads();

    for (int t = 0; t < TDIM; t++) {
        const int pp = t & 1;

        float acc[3][4];
#pragma unroll
        for (int gi = 0; gi < 3; gi++)
#pragma unroll
            for (int e = 0; e < 4; e++) acc[gi][e] = 0.0f;

        // A-frag stream: kb = kh*32 + it; word addr = ((kb*4+mt)*32+lane)*4.
        // 8-deep register ring (prefetch distance 8 covers L2 latency).
        const unsigned* hfp = g_hfrag16[pp] + kh * 16384 + ((mt * 32 + lane) << 2);
        uint4 ring[8];
#pragma unroll
        for (int i = 0; i < 8; i++)
            ring[i] = __ldcg((const uint4*)(hfp + i * 512));

        for (int base = 0; base < 32; base += 8) {
#pragma unroll
            for (int u = 0; u < 8; u++) {
                const int it = base + u;
                uint4 a = ring[u];
                if (it < 24)
                    ring[u] = __ldcg((const uint4*)(hfp + (it + 8) * 512));
                const int kb = kh * 32 + it;
                const unsigned* wk = Whs + kb * 192 + lane * 2;
#pragma unroll
                for (int gi = 0; gi < 3; gi++) {
                    uint2 b = *(const uint2*)(wk + gi * 64);
                    mma_f16_k16(acc[gi], a.x, a.y, a.z, a.w, b.x, b.y);
                }
            }
        }

        // 2-way K reduction via SMEM (stride-13 float rows, conflict-free).
        if (kh == 1) {
            float* rp = red + (mt * 32 + lane) * 13;
#pragma unroll
            for (int gi = 0; gi < 3; gi++)
#pragma unroll
                for (int e = 0; e < 4; e++) rp[gi * 4 + e] = acc[gi][e];
        }
        __syncthreads();

        float hy[4];
        if (kh == 0) {
            const float* rp = red + (mt * 32 + lane) * 13;
#pragma unroll
            for (int e = 0; e < 4; e++) {
                int part = e & 1, row = e >> 1;
                float pr = acc[0][e] + rp[0 * 4 + e] + bhv[0][part];
                float pu = acc[1][e] + rp[1 * 4 + e] + bhv[1][part];
                float pn = acc[2][e] + rp[2 * 4 + e] + bhv[2][part];
                float xr = part ? xv[0][row].y : xv[0][row].x;
                float xu = part ? xv[1][row].y : xv[1][row].x;
                float xn = part ? xv[2][row].y : xv[2][row].x;
                float rg = sigmoidf_(xr + pr);
                float ug = sigmoidf_(xu + pu);
                float ng = tanhf_(xn + rg * pn);
                hy[e] = ug * hpr[e] + (1.0f - ug) * ng;
                hpr[e] = hy[e];
            }
            // fp16 A-frag publish: this CTA owns HALF of kb-slot kbt=bid>>1.
            const int kbt = bid >> 1;
            const int ro = (bid & 1) * 2;
            unsigned* nf = g_hfrag16[pp ^ 1] + (((kbt * 4 + mt) * 32 + lane) << 2) + ro;
            *(uint2*)nf = make_uint2(packh2(hy[0], hy[1]), packh2(hy[2], hy[3]));
            // Order all 4 epilogue warps' STGs before arrive.
            asm volatile("bar.sync 1, 128;" ::: "memory");
        }

        const int target = t + 1;
        if (tid == 0) {
            __threadfence();
            // Two-level arrival tree: group (bid>>3) on its own 128B line,
            // last of 8 escalates to root, last of 16 publishes the flag.
            int o1 = atomicAdd(&g_sync[(bid >> 3) * 32], 1);
            if (o1 == target * 8 - 1) {
                int oR = atomicAdd(&g_sync[512], 1);
                if (oR == target * 16 - 1)
                    asm volatile("st.global.release.gpu.s32 [%0], %1;"
                                 :: "l"(&g_sync[544]), "r"(target) : "memory");
            }
        }

        // Hidden behind the barrier wait: hiddens output + next-x prefetch.
        if (kh == 0) {
            *(float2*)&hiddens[((size_t)b0r * TDIM + t) * HDIM + jj] =
                make_float2(hy[0], hy[1]);
            *(float2*)&hiddens[((size_t)b1r * TDIM + t) * HDIM + jj] =
                make_float2(hy[2], hy[3]);
            if (t + 1 < TDIM) {
#pragma unroll
                for (int gi = 0; gi < 3; gi++) {
                    xv[gi][0] = *(const float2*)&g_xall[((size_t)b0r * TDIM + t + 1) * G3 + gi * HDIM + jj];
                    xv[gi][1] = *(const float2*)&g_xall[((size_t)b1r * TDIM + t + 1) * G3 + gi * HDIM + jj];
                }
            }
        }

        if (tid == 0) {
            while (ld_acq(&g_sync[544]) < target) __nanosleep(20);
        }
        __syncthreads();
    }
}

__global__ void rec_init_kernel() {
    int i = blockIdx.x * blockDim.x + threadIdx.x;
    if (i < 576) g_sync[i] = 0;
    if (i < BDIM * HDIM / 2) g_hfrag16[0][i] = 0u;
}

extern "C" void kernel_launch(void* const* d_in, const int* in_sizes, int n_in,
                              void* d_out, int out_size)
{
    (void)in_sizes; (void)n_in; (void)out_size;
    const float* inputs = (const float*)d_in[0];
    const float* Wx = (const float*)d_in[1];
    const float* bx = (const float*)d_in[2];
    const float* Wh = (const float*)d_in[3];
    const float* bh = (const float*)d_in[4];
    const float* Wo = (const float*)d_in[5];
    const float* bo = (const float*)d_in[6];

    float* hiddens = (float*)d_out;                       // (B,T,H)
    float* proj    = hiddens + (size_t)MROWS * HDIM;      // (B,T,O)

    float* xall = nullptr;
    cudaGetSymbolAddress((void**)&xall, g_xall);

    // ncu alignment (harness pre-injects 2 launches; REC lands at -s 5 -c 1)
    dummy_kernel<<<1, 32>>>();

    // Phase 0: reset flags + zero h0 fragments (every launch/replay)
    rec_init_kernel<<<256, 256>>>();

    // Phase 1: x_all = inputs @ Wx^T + bx   (M=32768, N=3072, K=512)
    gemm_nt_kernel<<<dim3(G3 / 128, MROWS / 128), 256>>>(inputs, Wx, bx, xall, G3, DDIM);

    // Phase 2: persistent GRU recurrence -> hiddens (in d_out)
    const int rec_smem_bytes = 12288 * 4 + 1664 * 4;      // 55,808 B
    cudaFuncSetAttribute(gru_rec_kernel, cudaFuncAttributeMaxDynamicSharedMemorySize, rec_smem_bytes);
    gru_rec_kernel<<<RCTA, 256, rec_smem_bytes>>>(Wh, bh, hiddens);

    // Phase 3: out = hiddens @ Wo^T + bo   (M=32768, N=512, K=1024)
    gemm_nt_kernel<<<dim3(ODIM / 128, MROWS / 128), 256>>>(hiddens, Wo, bo, proj, ODIM, HDIM);
}